// round 13
// baseline (speedup 1.0000x reference)
#include <cuda_runtime.h>
#include <cuda_fp16.h>
#include <cstdint>

// ---------------------------------------------------------------------------
// UncertainTemporalAttention: N=8192, D=256. All GEMMs fp16 m16n8k16 mma.sync.
//   q = 0.125*(x Wq^T + bq); k = x Wk^T + bk; v = x Wv^T + bv; vv = xv Wvar^T + bvar
//   P' = exp(q k^T)/16 (fp16; scale cancels in ratios, avoids P'^2 overflow)
//   rs'_i = sum_j P'_ij
//   out_mean = ((P' v)/rs') Wo^T + bo;  out_var = (P'.^2 vv) / rs'^2
// R13: fp16 projections (inputs/weights pre-converted), fp16 tmp, 3-stage PV.
// ---------------------------------------------------------------------------

#define DEV_INLINE __device__ __forceinline__

constexpr int N_TOK = 8192;
constexpr int DIM   = 256;

__device__ __half g_xh  [N_TOK * DIM];
__device__ __half g_xvh [N_TOK * DIM];
__device__ __half g_Wqh [DIM * DIM];
__device__ __half g_Wkh [DIM * DIM];
__device__ __half g_Wvh [DIM * DIM];
__device__ __half g_Wvarh[DIM * DIM];
__device__ __half g_Woh [DIM * DIM];
__device__ __half g_q  [N_TOK * DIM];
__device__ __half g_k  [N_TOK * DIM];
__device__ __half g_vT [DIM * N_TOK];
__device__ __half g_vvT[DIM * N_TOK];
__device__ __half g_tmp[N_TOK * DIM];
__device__ float  g_rs [N_TOK];
__device__ float  g_rsp[(size_t)N_TOK * 64];
__device__ __half g_P  [(size_t)N_TOK * N_TOK];   // 128 MB

DEV_INLINE uint32_t smem_u32(const void* p) {
    return (uint32_t)__cvta_generic_to_shared(p);
}
DEV_INLINE void ldsm4(uint32_t* r, uint32_t a) {
    asm volatile("ldmatrix.sync.aligned.m8n8.x4.shared.b16 {%0,%1,%2,%3}, [%4];"
                 : "=r"(r[0]), "=r"(r[1]), "=r"(r[2]), "=r"(r[3]) : "r"(a));
}
DEV_INLINE void mma_f16(float* c, const uint32_t* a, uint32_t b0, uint32_t b1) {
    asm volatile(
        "mma.sync.aligned.m16n8k16.row.col.f32.f16.f16.f32 "
        "{%0,%1,%2,%3},{%4,%5,%6,%7},{%8,%9},{%0,%1,%2,%3};"
        : "+f"(c[0]), "+f"(c[1]), "+f"(c[2]), "+f"(c[3])
        : "r"(a[0]), "r"(a[1]), "r"(a[2]), "r"(a[3]), "r"(b0), "r"(b1));
}
DEV_INLINE void cp16(uint32_t s, const void* g) {
    asm volatile("cp.async.cg.shared.global [%0], [%1], 16;" :: "r"(s), "l"(g));
}
DEV_INLINE uint32_t hmul2(uint32_t a, uint32_t b) {
    uint32_t r;
    asm("mul.rn.f16x2 %0, %1, %2;" : "=r"(r) : "r"(a), "r"(b));
    return r;
}

// ===========================================================================
// fp32 -> fp16 conversion of inputs/weights (one-shot, ~16 MB)
// ===========================================================================
__global__ void cvt_fp16_kernel(
    const float* __restrict__ x_mean, const float* __restrict__ x_var,
    const float* __restrict__ Wq, const float* __restrict__ Wk,
    const float* __restrict__ Wv, const float* __restrict__ Wvar,
    const float* __restrict__ Wo,
    __half* __restrict__ xh, __half* __restrict__ xvh,
    __half* __restrict__ wq, __half* __restrict__ wk,
    __half* __restrict__ wv, __half* __restrict__ wvar,
    __half* __restrict__ wo)
{
    const float* src; __half* dst; int n;
    switch (blockIdx.y) {
        case 0: src = x_mean; dst = xh;   n = N_TOK * DIM; break;
        case 1: src = x_var;  dst = xvh;  n = N_TOK * DIM; break;
        case 2: src = Wq;     dst = wq;   n = DIM * DIM;   break;
        case 3: src = Wk;     dst = wk;   n = DIM * DIM;   break;
        case 4: src = Wv;     dst = wv;   n = DIM * DIM;   break;
        case 5: src = Wvar;   dst = wvar; n = DIM * DIM;   break;
        default: src = Wo;    dst = wo;   n = DIM * DIM;   break;
    }
    const int n2 = n >> 1;
    for (int i = blockIdx.x * blockDim.x + threadIdx.x; i < n2;
         i += gridDim.x * blockDim.x) {
        float2 v = reinterpret_cast<const float2*>(src)[i];
        reinterpret_cast<__half2*>(dst)[i] = __floats2half2_rn(v.x, v.y);
    }
}

// ===========================================================================
// fp16 projection GEMM: C = (A[M,256] B[256,256]^T + bias) * scale.
// CTA 128x64, 256 thr (2x4 warps), warp 64x16. K=256 halfs, 4 chunks of 64.
// Stage: A 16K + B 8K = 24K; 2 stages = 48K; 2 CTA/SM.
// ===========================================================================
template <bool TRANS, bool OUT_HALF>
__global__ void __launch_bounds__(256, 2)
proj_h_kernel(const __half* __restrict__ A0, const __half* __restrict__ B0,
              const float* __restrict__ bias0, void* __restrict__ C0, float scale0,
              const __half* __restrict__ A1, const __half* __restrict__ B1,
              const float* __restrict__ bias1, void* __restrict__ C1, float scale1,
              int M)
{
    const __half* A   = blockIdx.z ? A1 : A0;
    const __half* B   = blockIdx.z ? B1 : B0;
    const float* bias = blockIdx.z ? bias1 : bias0;
    void*        C    = blockIdx.z ? C1 : C0;
    const float scale = blockIdx.z ? scale1 : scale0;

    extern __shared__ char smem_raw[];
    const uint32_t s_base = smem_u32(smem_raw);
    const int tid = threadIdx.x;
    const int warp = tid >> 5, lane = tid & 31;
    const int wm = warp >> 2, wn = warp & 3;
    const int bm = blockIdx.y, bn = blockIdx.x;

    const __half* Ab = A + (size_t)bm * 128 * DIM;
    const __half* Bb = B + (size_t)bn * 64 * DIM;

    float c[4][2][4];
#pragma unroll
    for (int i = 0; i < 4; i++)
#pragma unroll
        for (int j = 0; j < 2; j++)
#pragma unroll
            for (int l = 0; l < 4; l++) c[i][j][l] = 0.f;

    auto issue = [&](int stage, int kc) {
        const uint32_t sA = s_base + (uint32_t)stage * 24576u;
        const uint32_t sB = sA + 16384u;
        const int k0 = kc * 64;
#pragma unroll
        for (int i = 0; i < 4; i++) {        // A: 128 rows x 128B
            int v = tid + i * 256; int row = v >> 3, ch = v & 7;
            uint32_t off = (uint32_t)(row * 128 + ((ch ^ (row & 7)) << 4));
            cp16(sA + off, Ab + (size_t)row * DIM + k0 + ch * 8);
        }
#pragma unroll
        for (int i = 0; i < 2; i++) {        // B: 64 rows x 128B
            int v = tid + i * 256; int row = v >> 3, ch = v & 7;
            uint32_t off = (uint32_t)(row * 128 + ((ch ^ (row & 7)) << 4));
            cp16(sB + off, Bb + (size_t)row * DIM + k0 + ch * 8);
        }
        asm volatile("cp.async.commit_group;");
    };

    auto compute = [&](int stage) {
        const uint32_t sA = s_base + (uint32_t)stage * 24576u;
        const uint32_t sB = sA + 16384u;
        const int lg = lane >> 3, li = lane & 7;
#pragma unroll
        for (int s = 0; s < 4; s++) {
            const int ch = s * 2 + (lg >> 1);
            uint32_t a[4][4];
#pragma unroll
            for (int mt = 0; mt < 4; mt++) {
                int row = wm * 64 + mt * 16 + (lg & 1) * 8 + li;
                ldsm4(a[mt], sA + row * 128 + ((ch ^ (row & 7)) << 4));
            }
            uint32_t b[4];
            {
                int row = wn * 16 + (lg & 1) * 8 + li;
                ldsm4(b, sB + row * 128 + ((ch ^ (row & 7)) << 4));
            }
#pragma unroll
            for (int mt = 0; mt < 4; mt++)
#pragma unroll
                for (int nt = 0; nt < 2; nt++)
                    mma_f16(c[mt][nt], a[mt], b[nt], b[nt + 2]);
        }
    };

    const int nk = DIM / 64;   // 4
    issue(0, 0);
    for (int kc = 0; kc < nk; kc++) {
        if (kc + 1 < nk) { issue((kc + 1) & 1, kc + 1); asm volatile("cp.async.wait_group 1;"); }
        else             { asm volatile("cp.async.wait_group 0;"); }
        __syncthreads();
        compute(kc & 1);
        __syncthreads();
    }

    const int gr0 = bm * 128 + wm * 64;
    const int gc0 = bn * 64 + wn * 16;
#pragma unroll
    for (int mt = 0; mt < 4; mt++)
#pragma unroll
        for (int rr = 0; rr < 2; rr++) {
            int row = gr0 + mt * 16 + rr * 8 + (lane >> 2);
#pragma unroll
            for (int nt = 0; nt < 2; nt++) {
                int col = gc0 + nt * 8 + (lane & 3) * 2;
                float v0 = (c[mt][nt][rr * 2 + 0] + bias[col])     * scale;
                float v1 = (c[mt][nt][rr * 2 + 1] + bias[col + 1]) * scale;
                if (OUT_HALF) {
                    __half* Ch = (__half*)C;
                    if (TRANS) {
                        Ch[(size_t)col * M + row]       = __float2half_rn(v0);
                        Ch[(size_t)(col + 1) * M + row] = __float2half_rn(v1);
                    } else {
                        *reinterpret_cast<__half2*>(&Ch[(size_t)row * DIM + col]) =
                            __floats2half2_rn(v0, v1);
                    }
                } else {
                    float* Cf = (float*)C;
                    *reinterpret_cast<float2*>(&Cf[(size_t)row * DIM + col]) =
                        make_float2(v0, v1);
                }
            }
        }
}

// ===========================================================================
// QK^T (fp16) + exp/16 + rowsum partials + half P store.
// CTA 128x128, 256 thr (2x4 warps), warp tile 64x32. K=256 halfs, 4 chunks of 64.
// Stage: A 16K + B 16K = 32K; 2 stages = 64K; 2 CTA/SM.
// ===========================================================================
__global__ void __launch_bounds__(256, 2)
qk_exp_kernel(const __half* __restrict__ Q, const __half* __restrict__ Km,
              __half* __restrict__ P, float* __restrict__ rsp)
{
    extern __shared__ char smem_raw[];
    const uint32_t s_base = smem_u32(smem_raw);
    __shared__ float rsum[4][128];

    const int tid = threadIdx.x;
    const int warp = tid >> 5, lane = tid & 31;
    const int wm = warp >> 2, wn = warp & 3;
    const int bn = blockIdx.x, bm = blockIdx.y;

    const __half* Ab = Q  + (size_t)bm * 128 * DIM;
    const __half* Bb = Km + (size_t)bn * 128 * DIM;

    float c[4][4][4];
#pragma unroll
    for (int i = 0; i < 4; i++)
#pragma unroll
        for (int j = 0; j < 4; j++)
#pragma unroll
            for (int l = 0; l < 4; l++) c[i][j][l] = 0.f;

    auto issue = [&](int stage, int kc) {
        const uint32_t sA = s_base + (uint32_t)stage * 32768u;
        const uint32_t sB = sA + 16384u;
        const int k0 = kc * 64;
#pragma unroll
        for (int i = 0; i < 4; i++) {
            int v = tid + i * 256; int row = v >> 3, ch = v & 7;
            uint32_t off = (uint32_t)(row * 128 + ((ch ^ (row & 7)) << 4));
            cp16(sA + off, Ab + (size_t)row * DIM + k0 + ch * 8);
            cp16(sB + off, Bb + (size_t)row * DIM + k0 + ch * 8);
        }
        asm volatile("cp.async.commit_group;");
    };

    auto compute = [&](int stage) {
        const uint32_t sA = s_base + (uint32_t)stage * 32768u;
        const uint32_t sB = sA + 16384u;
        const int lg = lane >> 3, li = lane & 7;
#pragma unroll
        for (int s = 0; s < 4; s++) {
            const int ch = s * 2 + (lg >> 1);
            uint32_t a[4][4];
#pragma unroll
            for (int mt = 0; mt < 4; mt++) {
                int row = wm * 64 + mt * 16 + (lg & 1) * 8 + li;
                ldsm4(a[mt], sA + row * 128 + ((ch ^ (row & 7)) << 4));
            }
            uint32_t b[2][4];
#pragma unroll
            for (int p = 0; p < 2; p++) {
                int row = wn * 32 + p * 16 + (lg & 1) * 8 + li;
                ldsm4(b[p], sB + row * 128 + ((ch ^ (row & 7)) << 4));
            }
#pragma unroll
            for (int mt = 0; mt < 4; mt++)
#pragma unroll
                for (int nt = 0; nt < 4; nt++) {
                    const int p = nt >> 1, o = nt & 1;
                    mma_f16(c[mt][nt], a[mt], b[p][o], b[p][o + 2]);
                }
        }
    };

    const int nk = DIM / 64;   // 4
    issue(0, 0);
    for (int kc = 0; kc < nk; kc++) {
        if (kc + 1 < nk) { issue((kc + 1) & 1, kc + 1); asm volatile("cp.async.wait_group 1;"); }
        else             { asm volatile("cp.async.wait_group 0;"); }
        __syncthreads();
        compute(kc & 1);
        __syncthreads();
    }

    const int gr0 = bm * 128 + wm * 64;
    const int gc0 = bn * 128 + wn * 32;
#pragma unroll
    for (int mt = 0; mt < 4; mt++)
#pragma unroll
        for (int rr = 0; rr < 2; rr++) {
            int row = gr0 + mt * 16 + rr * 8 + (lane >> 2);
            float rowpart = 0.f;
#pragma unroll
            for (int nt = 0; nt < 4; nt++) {
                int col = gc0 + nt * 8 + (lane & 3) * 2;
                float e0 = __expf(c[mt][nt][rr * 2 + 0]) * 0.0625f;
                float e1 = __expf(c[mt][nt][rr * 2 + 1]) * 0.0625f;
                __half2 h = __floats2half2_rn(e0, e1);
                *reinterpret_cast<__half2*>(&P[(size_t)row * N_TOK + col]) = h;
                float2 f = __half22float2(h);
                rowpart += f.x + f.y;
            }
            rowpart += __shfl_xor_sync(0xffffffffu, rowpart, 1);
            rowpart += __shfl_xor_sync(0xffffffffu, rowpart, 2);
            if ((lane & 3) == 0)
                rsum[wn][wm * 64 + mt * 16 + rr * 8 + (lane >> 2)] = rowpart;
        }
    __syncthreads();
    if (tid < 128) {
        float s = rsum[0][tid] + rsum[1][tid] + rsum[2][tid] + rsum[3][tid];
        rsp[(size_t)(bm * 128 + tid) * 64 + bn] = s;
    }
}

__global__ void rs_reduce_kernel(const float* __restrict__ rsp, float* __restrict__ rs)
{
    const int row = blockIdx.x * 256 + threadIdx.x;
    const float4* p = reinterpret_cast<const float4*>(rsp + (size_t)row * 64);
    float s = 0.f;
#pragma unroll
    for (int i = 0; i < 16; i++) {
        float4 v = p[i];
        s += (v.x + v.y) + (v.z + v.w);
    }
    rs[row] = s;
}

// ===========================================================================
// Fused PV (fp16): tmp = (P' v)/rs' (fp16) ; out_var = (P'^2 vv)/rs'^2 (fp32).
// CTA 128x64, 256 thr (2x4 warps), warp tile 64x16 per path.
// Stage: A 16K | B1 8K | B2 8K = 32K; 3 stages = 96K; 2 CTA/SM.
// ===========================================================================
__global__ void __launch_bounds__(256, 2)
fused_pv_kernel(const __half* __restrict__ P, const __half* __restrict__ vT,
                const __half* __restrict__ vvT, const float* __restrict__ rs,
                __half* __restrict__ tmp, float* __restrict__ out_var)
{
    extern __shared__ char smem_raw[];
    const uint32_t s_base = smem_u32(smem_raw);
    const int tid = threadIdx.x;
    const int warp = tid >> 5, lane = tid & 31;
    const int wm = warp >> 2, wn = warp & 3;
    const int bn = blockIdx.x, bm = blockIdx.y;

    const __half* Ab  = P   + (size_t)bm * 128 * N_TOK;
    const __half* B1b = vT  + (size_t)bn * 64 * N_TOK;
    const __half* B2b = vvT + (size_t)bn * 64 * N_TOK;

    float cm[4][2][4], cv[4][2][4];
#pragma unroll
    for (int i = 0; i < 4; i++)
#pragma unroll
        for (int j = 0; j < 2; j++)
#pragma unroll
            for (int l = 0; l < 4; l++) { cm[i][j][l] = 0.f; cv[i][j][l] = 0.f; }

    auto stage_of = [](int c) { return c % 3; };

    auto issue = [&](int c) {
        const uint32_t sA  = s_base + (uint32_t)(c % 3) * 32768u;
        const uint32_t sB1 = sA + 16384u;
        const uint32_t sB2 = sA + 24576u;
        const int k0 = c * 64;
#pragma unroll
        for (int i = 0; i < 4; i++) {        // A: 128 rows x 128B = 16K
            int v = tid + i * 256; int row = v >> 3, ch = v & 7;
            uint32_t off = (uint32_t)(row * 128 + ((ch ^ (row & 7)) << 4));
            cp16(sA + off, Ab + (size_t)row * N_TOK + k0 + ch * 8);
        }
#pragma unroll
        for (int i = 0; i < 2; i++) {        // B1/B2: 64 rows x 128B = 8K each
            int v = tid + i * 256; int row = v >> 3, ch = v & 7;
            uint32_t off = (uint32_t)(row * 128 + ((ch ^ (row & 7)) << 4));
            cp16(sB1 + off, B1b + (size_t)row * N_TOK + k0 + ch * 8);
            cp16(sB2 + off, B2b + (size_t)row * N_TOK + k0 + ch * 8);
        }
        asm volatile("cp.async.commit_group;");
    };

    auto compute = [&](int c) {
        const uint32_t sA  = s_base + (uint32_t)(c % 3) * 32768u;
        const uint32_t sB1 = sA + 16384u;
        const uint32_t sB2 = sA + 24576u;
        const int lg = lane >> 3, li = lane & 7;
#pragma unroll
        for (int s = 0; s < 4; s++) {
            const int ch = s * 2 + (lg >> 1);
            uint32_t a[4][4], a2[4][4];
#pragma unroll
            for (int mt = 0; mt < 4; mt++) {
                int row = wm * 64 + mt * 16 + (lg & 1) * 8 + li;
                ldsm4(a[mt], sA + row * 128 + ((ch ^ (row & 7)) << 4));
#pragma unroll
                for (int q = 0; q < 4; q++) a2[mt][q] = hmul2(a[mt][q], a[mt][q]);
            }
            uint32_t b1[4], b2[4];
            {
                int row = wn * 16 + (lg & 1) * 8 + li;
                uint32_t off = (uint32_t)(row * 128 + ((ch ^ (row & 7)) << 4));
                ldsm4(b1, sB1 + off);
                ldsm4(b2, sB2 + off);
            }
#pragma unroll
            for (int mt = 0; mt < 4; mt++)
#pragma unroll
                for (int nt = 0; nt < 2; nt++) {
                    mma_f16(cm[mt][nt], a[mt],  b1[nt], b1[nt + 2]);
                    mma_f16(cv[mt][nt], a2[mt], b2[nt], b2[nt + 2]);
                }
        }
    };

    const int nk = N_TOK / 64;   // 128
    issue(0); issue(1);
    for (int c = 0; c < nk; c++) {
        if (c + 2 < nk) issue(c + 2);
        const int rem = nk - 1 - c;
        if (rem >= 2)      asm volatile("cp.async.wait_group 2;");
        else if (rem == 1) asm volatile("cp.async.wait_group 1;");
        else               asm volatile("cp.async.wait_group 0;");
        __syncthreads();
        compute(c);
        __syncthreads();
    }
    (void)stage_of;

    const int gr0 = bm * 128 + wm * 64;
    const int gc0 = bn * 64 + wn * 16;
#pragma unroll
    for (int mt = 0; mt < 4; mt++)
#pragma unroll
        for (int rr = 0; rr < 2; rr++) {
            int row = gr0 + mt * 16 + rr * 8 + (lane >> 2);
            float rfac = 1.f / rs[row];
            float rfac2 = rfac * rfac;
#pragma unroll
            for (int nt = 0; nt < 2; nt++) {
                int col = gc0 + nt * 8 + (lane & 3) * 2;
                float m0 = cm[mt][nt][rr * 2 + 0] * rfac;
                float m1 = cm[mt][nt][rr * 2 + 1] * rfac;
                *reinterpret_cast<__half2*>(&tmp[(size_t)row * DIM + col]) =
                    __floats2half2_rn(m0, m1);
                float v0 = cv[mt][nt][rr * 2 + 0] * rfac2;
                float v1 = cv[mt][nt][rr * 2 + 1] * rfac2;
                *reinterpret_cast<float2*>(&out_var[(size_t)row * DIM + col]) =
                    make_float2(v0, v1);
            }
        }
}

// ===========================================================================
extern "C" void kernel_launch(void* const* d_in, const int* in_sizes, int n_in,
                              void* d_out, int out_size)
{
    (void)in_sizes; (void)n_in; (void)out_size;
    const float* x_mean = (const float*)d_in[0];
    const float* x_var  = (const float*)d_in[1];
    const float* Wq = (const float*)d_in[4];  const float* bq = (const float*)d_in[5];
    const float* Wk = (const float*)d_in[6];  const float* bk = (const float*)d_in[7];
    const float* Wv = (const float*)d_in[8];  const float* bv = (const float*)d_in[9];
    const float* Wo = (const float*)d_in[10]; const float* bo = (const float*)d_in[11];
    const float* Wvar = (const float*)d_in[12]; const float* bvar = (const float*)d_in[13];

    float* out_mean = (float*)d_out;
    float* out_var  = out_mean + (size_t)N_TOK * DIM;

    __half *xh, *xvh, *wq, *wk, *wv, *wvar, *wo;
    __half *q, *k, *vT, *vvT, *P, *tmp;
    float *rs, *rsp;
    cudaGetSymbolAddress((void**)&xh,   g_xh);
    cudaGetSymbolAddress((void**)&xvh,  g_xvh);
    cudaGetSymbolAddress((void**)&wq,   g_Wqh);
    cudaGetSymbolAddress((void**)&wk,   g_Wkh);
    cudaGetSymbolAddress((void**)&wv,   g_Wvh);
    cudaGetSymbolAddress((void**)&wvar, g_Wvarh);
    cudaGetSymbolAddress((void**)&wo,   g_Woh);
    cudaGetSymbolAddress((void**)&q,    g_q);
    cudaGetSymbolAddress((void**)&k,    g_k);
    cudaGetSymbolAddress((void**)&vT,   g_vT);
    cudaGetSymbolAddress((void**)&vvT,  g_vvT);
    cudaGetSymbolAddress((void**)&tmp,  g_tmp);
    cudaGetSymbolAddress((void**)&P,    g_P);
    cudaGetSymbolAddress((void**)&rs,   g_rs);
    cudaGetSymbolAddress((void**)&rsp,  g_rsp);

    const int SM_PROJ = 49152;   // (16K+8K)*2
    const int SM_QK   = 65536;   // (16K+16K)*2
    const int SM_PV   = 98304;   // (16K+8K+8K)*3

    cudaFuncSetAttribute((const void*)proj_h_kernel<false, true >, cudaFuncAttributeMaxDynamicSharedMemorySize, SM_PROJ);
    cudaFuncSetAttribute((const void*)proj_h_kernel<true,  true >, cudaFuncAttributeMaxDynamicSharedMemorySize, SM_PROJ);
    cudaFuncSetAttribute((const void*)proj_h_kernel<false, false>, cudaFuncAttributeMaxDynamicSharedMemorySize, SM_PROJ);
    cudaFuncSetAttribute((const void*)qk_exp_kernel,   cudaFuncAttributeMaxDynamicSharedMemorySize, SM_QK);
    cudaFuncSetAttribute((const void*)fused_pv_kernel, cudaFuncAttributeMaxDynamicSharedMemorySize, SM_PV);

    // convert inputs + weights to fp16
    cvt_fp16_kernel<<<dim3(128, 7), 256>>>(
        x_mean, x_var, Wq, Wk, Wv, Wvar, Wo,
        xh, xvh, wq, wk, wv, wvar, wo);

    dim3 gProj2(DIM / 64, N_TOK / 128, 2);  // (4, 64, 2)
    dim3 gProj1(DIM / 64, N_TOK / 128, 1);
    dim3 gQK(N_TOK / 128, N_TOK / 128);     // (64, 64)
    dim3 gPV(DIM / 64, N_TOK / 128);        // (4, 64)

    // projections: q (x0.125) + k; vT + vvT (transposed)
    proj_h_kernel<false, true><<<gProj2, 256, SM_PROJ>>>(
        xh, wq, bq, q, 0.125f,  xh, wk, bk, k, 1.f, N_TOK);
    proj_h_kernel<true, true><<<gProj2, 256, SM_PROJ>>>(
        xh, wv, bv, vT, 1.f,    xvh, wvar, bvar, vvT, 1.f, N_TOK);

    qk_exp_kernel<<<gQK, 256, SM_QK>>>(q, k, P, rsp);
    rs_reduce_kernel<<<N_TOK / 256, 256>>>(rsp, rs);

    fused_pv_kernel<<<gPV, 256, SM_PV>>>(P, vT, vvT, rs, tmp, out_var);

    proj_h_kernel<false, false><<<gProj1, 256, SM_PROJ>>>(
        tmp, wo, bo, out_mean, 1.f, tmp, wo, bo, out_mean, 1.f, N_TOK);
}

// round 15
// speedup vs baseline: 1.5662x; 1.5662x over previous
#include <cuda_runtime.h>
#include <cuda_fp16.h>
#include <cstdint>

// ---------------------------------------------------------------------------
// UncertainTemporalAttention: N=8192, D=256. All GEMMs fp16 m16n8k16 mma.sync.
//   q = 0.125*(x Wq^T + bq); k = x Wk^T + bk; v = x Wv^T + bv; vv = xv Wvar^T + bvar
//   P' = exp(q k^T)/16 (fp16; scale cancels in ratios, avoids P'^2 overflow)
//   rs'_i = sum_j P'_ij
//   out_mean = ((P' v)/rs') Wo^T + bo;  out_var = (P'.^2 vv) / rs'^2
// R14: R12 geometry everywhere (PV back to 2-stage 64K) + fp16 projections
// and fp16 tmp (the only R13 changes retained).
// ---------------------------------------------------------------------------

#define DEV_INLINE __device__ __forceinline__

constexpr int N_TOK = 8192;
constexpr int DIM   = 256;

__device__ __half g_xh  [N_TOK * DIM];
__device__ __half g_xvh [N_TOK * DIM];
__device__ __half g_Wqh [DIM * DIM];
__device__ __half g_Wkh [DIM * DIM];
__device__ __half g_Wvh [DIM * DIM];
__device__ __half g_Wvarh[DIM * DIM];
__device__ __half g_Woh [DIM * DIM];
__device__ __half g_q  [N_TOK * DIM];
__device__ __half g_k  [N_TOK * DIM];
__device__ __half g_vT [DIM * N_TOK];
__device__ __half g_vvT[DIM * N_TOK];
__device__ __half g_tmp[N_TOK * DIM];
__device__ float  g_rs [N_TOK];
__device__ float  g_rsp[(size_t)N_TOK * 64];
__device__ __half g_P  [(size_t)N_TOK * N_TOK];   // 128 MB

DEV_INLINE uint32_t smem_u32(const void* p) {
    return (uint32_t)__cvta_generic_to_shared(p);
}
DEV_INLINE void ldsm4(uint32_t* r, uint32_t a) {
    asm volatile("ldmatrix.sync.aligned.m8n8.x4.shared.b16 {%0,%1,%2,%3}, [%4];"
                 : "=r"(r[0]), "=r"(r[1]), "=r"(r[2]), "=r"(r[3]) : "r"(a));
}
DEV_INLINE void mma_f16(float* c, const uint32_t* a, uint32_t b0, uint32_t b1) {
    asm volatile(
        "mma.sync.aligned.m16n8k16.row.col.f32.f16.f16.f32 "
        "{%0,%1,%2,%3},{%4,%5,%6,%7},{%8,%9},{%0,%1,%2,%3};"
        : "+f"(c[0]), "+f"(c[1]), "+f"(c[2]), "+f"(c[3])
        : "r"(a[0]), "r"(a[1]), "r"(a[2]), "r"(a[3]), "r"(b0), "r"(b1));
}
DEV_INLINE void cp16(uint32_t s, const void* g) {
    asm volatile("cp.async.cg.shared.global [%0], [%1], 16;" :: "r"(s), "l"(g));
}
DEV_INLINE uint32_t hmul2(uint32_t a, uint32_t b) {
    uint32_t r;
    asm("mul.rn.f16x2 %0, %1, %2;" : "=r"(r) : "r"(a), "r"(b));
    return r;
}

// ===========================================================================
// fp32 -> fp16 conversion of inputs/weights (one-shot, ~16 MB)
// ===========================================================================
__global__ void cvt_fp16_kernel(
    const float* __restrict__ x_mean, const float* __restrict__ x_var,
    const float* __restrict__ Wq, const float* __restrict__ Wk,
    const float* __restrict__ Wv, const float* __restrict__ Wvar,
    const float* __restrict__ Wo,
    __half* __restrict__ xh, __half* __restrict__ xvh,
    __half* __restrict__ wq, __half* __restrict__ wk,
    __half* __restrict__ wv, __half* __restrict__ wvar,
    __half* __restrict__ wo)
{
    const float* src; __half* dst; int n;
    switch (blockIdx.y) {
        case 0: src = x_mean; dst = xh;   n = N_TOK * DIM; break;
        case 1: src = x_var;  dst = xvh;  n = N_TOK * DIM; break;
        case 2: src = Wq;     dst = wq;   n = DIM * DIM;   break;
        case 3: src = Wk;     dst = wk;   n = DIM * DIM;   break;
        case 4: src = Wv;     dst = wv;   n = DIM * DIM;   break;
        case 5: src = Wvar;   dst = wvar; n = DIM * DIM;   break;
        default: src = Wo;    dst = wo;   n = DIM * DIM;   break;
    }
    const int n2 = n >> 1;
    for (int i = blockIdx.x * blockDim.x + threadIdx.x; i < n2;
         i += gridDim.x * blockDim.x) {
        float2 v = reinterpret_cast<const float2*>(src)[i];
        reinterpret_cast<__half2*>(dst)[i] = __floats2half2_rn(v.x, v.y);
    }
}

// ===========================================================================
// fp16 projection GEMM: C = (A[M,256] B[256,256]^T + bias) * scale.
// CTA 128x64, 256 thr (2x4 warps), warp 64x16. K=256 halfs, 4 chunks of 64.
// Stage: A 16K + B 8K = 24K; 2 stages = 48K; 2 CTA/SM.
// ===========================================================================
template <bool TRANS, bool OUT_HALF>
__global__ void __launch_bounds__(256, 2)
proj_h_kernel(const __half* __restrict__ A0, const __half* __restrict__ B0,
              const float* __restrict__ bias0, void* __restrict__ C0, float scale0,
              const __half* __restrict__ A1, const __half* __restrict__ B1,
              const float* __restrict__ bias1, void* __restrict__ C1, float scale1,
              int M)
{
    const __half* A   = blockIdx.z ? A1 : A0;
    const __half* B   = blockIdx.z ? B1 : B0;
    const float* bias = blockIdx.z ? bias1 : bias0;
    void*        C    = blockIdx.z ? C1 : C0;
    const float scale = blockIdx.z ? scale1 : scale0;

    extern __shared__ char smem_raw[];
    const uint32_t s_base = smem_u32(smem_raw);
    const int tid = threadIdx.x;
    const int warp = tid >> 5, lane = tid & 31;
    const int wm = warp >> 2, wn = warp & 3;
    const int bm = blockIdx.y, bn = blockIdx.x;

    const __half* Ab = A + (size_t)bm * 128 * DIM;
    const __half* Bb = B + (size_t)bn * 64 * DIM;

    float c[4][2][4];
#pragma unroll
    for (int i = 0; i < 4; i++)
#pragma unroll
        for (int j = 0; j < 2; j++)
#pragma unroll
            for (int l = 0; l < 4; l++) c[i][j][l] = 0.f;

    auto issue = [&](int stage, int kc) {
        const uint32_t sA = s_base + (uint32_t)stage * 24576u;
        const uint32_t sB = sA + 16384u;
        const int k0 = kc * 64;
#pragma unroll
        for (int i = 0; i < 4; i++) {        // A: 128 rows x 128B
            int v = tid + i * 256; int row = v >> 3, ch = v & 7;
            uint32_t off = (uint32_t)(row * 128 + ((ch ^ (row & 7)) << 4));
            cp16(sA + off, Ab + (size_t)row * DIM + k0 + ch * 8);
        }
#pragma unroll
        for (int i = 0; i < 2; i++) {        // B: 64 rows x 128B
            int v = tid + i * 256; int row = v >> 3, ch = v & 7;
            uint32_t off = (uint32_t)(row * 128 + ((ch ^ (row & 7)) << 4));
            cp16(sB + off, Bb + (size_t)row * DIM + k0 + ch * 8);
        }
        asm volatile("cp.async.commit_group;");
    };

    auto compute = [&](int stage) {
        const uint32_t sA = s_base + (uint32_t)stage * 24576u;
        const uint32_t sB = sA + 16384u;
        const int lg = lane >> 3, li = lane & 7;
#pragma unroll
        for (int s = 0; s < 4; s++) {
            const int ch = s * 2 + (lg >> 1);
            uint32_t a[4][4];
#pragma unroll
            for (int mt = 0; mt < 4; mt++) {
                int row = wm * 64 + mt * 16 + (lg & 1) * 8 + li;
                ldsm4(a[mt], sA + row * 128 + ((ch ^ (row & 7)) << 4));
            }
            uint32_t b[4];
            {
                int row = wn * 16 + (lg & 1) * 8 + li;
                int chb = s * 2 + (lg >> 1);
                ldsm4(b, sB + row * 128 + ((chb ^ (row & 7)) << 4));
            }
#pragma unroll
            for (int mt = 0; mt < 4; mt++)
#pragma unroll
                for (int nt = 0; nt < 2; nt++)
                    mma_f16(c[mt][nt], a[mt], b[nt], b[nt + 2]);
        }
    };

    const int nk = DIM / 64;   // 4
    issue(0, 0);
    for (int kc = 0; kc < nk; kc++) {
        if (kc + 1 < nk) { issue((kc + 1) & 1, kc + 1); asm volatile("cp.async.wait_group 1;"); }
        else             { asm volatile("cp.async.wait_group 0;"); }
        __syncthreads();
        compute(kc & 1);
        __syncthreads();
    }

    const int gr0 = bm * 128 + wm * 64;
    const int gc0 = bn * 64 + wn * 16;
#pragma unroll
    for (int mt = 0; mt < 4; mt++)
#pragma unroll
        for (int rr = 0; rr < 2; rr++) {
            int row = gr0 + mt * 16 + rr * 8 + (lane >> 2);
#pragma unroll
            for (int nt = 0; nt < 2; nt++) {
                int col = gc0 + nt * 8 + (lane & 3) * 2;
                float v0 = (c[mt][nt][rr * 2 + 0] + bias[col])     * scale;
                float v1 = (c[mt][nt][rr * 2 + 1] + bias[col + 1]) * scale;
                if (OUT_HALF) {
                    __half* Ch = (__half*)C;
                    if (TRANS) {
                        Ch[(size_t)col * M + row]       = __float2half_rn(v0);
                        Ch[(size_t)(col + 1) * M + row] = __float2half_rn(v1);
                    } else {
                        *reinterpret_cast<__half2*>(&Ch[(size_t)row * DIM + col]) =
                            __floats2half2_rn(v0, v1);
                    }
                } else {
                    float* Cf = (float*)C;
                    *reinterpret_cast<float2*>(&Cf[(size_t)row * DIM + col]) =
                        make_float2(v0, v1);
                }
            }
        }
}

// ===========================================================================
// QK^T (fp16) + exp/16 + rowsum partials + half P store.  (R12-identical)
// CTA 128x128, 256 thr (2x4 warps), warp tile 64x32. K=256 halfs, 4 chunks of 64.
// Stage: A 16K + B 16K = 32K; 2 stages = 64K; 2 CTA/SM.
// ===========================================================================
__global__ void __launch_bounds__(256, 2)
qk_exp_kernel(const __half* __restrict__ Q, const __half* __restrict__ Km,
              __half* __restrict__ P, float* __restrict__ rsp)
{
    extern __shared__ char smem_raw[];
    const uint32_t s_base = smem_u32(smem_raw);
    __shared__ float rsum[4][128];

    const int tid = threadIdx.x;
    const int warp = tid >> 5, lane = tid & 31;
    const int wm = warp >> 2, wn = warp & 3;
    const int bn = blockIdx.x, bm = blockIdx.y;

    const __half* Ab = Q  + (size_t)bm * 128 * DIM;
    const __half* Bb = Km + (size_t)bn * 128 * DIM;

    float c[4][4][4];
#pragma unroll
    for (int i = 0; i < 4; i++)
#pragma unroll
        for (int j = 0; j < 4; j++)
#pragma unroll
            for (int l = 0; l < 4; l++) c[i][j][l] = 0.f;

    auto issue = [&](int stage, int kc) {
        const uint32_t sA = s_base + (uint32_t)stage * 32768u;
        const uint32_t sB = sA + 16384u;
        const int k0 = kc * 64;
#pragma unroll
        for (int i = 0; i < 4; i++) {
            int v = tid + i * 256; int row = v >> 3, ch = v & 7;
            uint32_t off = (uint32_t)(row * 128 + ((ch ^ (row & 7)) << 4));
            cp16(sA + off, Ab + (size_t)row * DIM + k0 + ch * 8);
            cp16(sB + off, Bb + (size_t)row * DIM + k0 + ch * 8);
        }
        asm volatile("cp.async.commit_group;");
    };

    auto compute = [&](int stage) {
        const uint32_t sA = s_base + (uint32_t)stage * 32768u;
        const uint32_t sB = sA + 16384u;
        const int lg = lane >> 3, li = lane & 7;
#pragma unroll
        for (int s = 0; s < 4; s++) {
            const int ch = s * 2 + (lg >> 1);
            uint32_t a[4][4];
#pragma unroll
            for (int mt = 0; mt < 4; mt++) {
                int row = wm * 64 + mt * 16 + (lg & 1) * 8 + li;
                ldsm4(a[mt], sA + row * 128 + ((ch ^ (row & 7)) << 4));
            }
            uint32_t b[2][4];
#pragma unroll
            for (int p = 0; p < 2; p++) {
                int row = wn * 32 + p * 16 + (lg & 1) * 8 + li;
                ldsm4(b[p], sB + row * 128 + ((ch ^ (row & 7)) << 4));
            }
#pragma unroll
            for (int mt = 0; mt < 4; mt++)
#pragma unroll
                for (int nt = 0; nt < 4; nt++) {
                    const int p = nt >> 1, o = nt & 1;
                    mma_f16(c[mt][nt], a[mt], b[p][o], b[p][o + 2]);
                }
        }
    };

    const int nk = DIM / 64;   // 4
    issue(0, 0);
    for (int kc = 0; kc < nk; kc++) {
        if (kc + 1 < nk) { issue((kc + 1) & 1, kc + 1); asm volatile("cp.async.wait_group 1;"); }
        else             { asm volatile("cp.async.wait_group 0;"); }
        __syncthreads();
        compute(kc & 1);
        __syncthreads();
    }

    const int gr0 = bm * 128 + wm * 64;
    const int gc0 = bn * 128 + wn * 32;
#pragma unroll
    for (int mt = 0; mt < 4; mt++)
#pragma unroll
        for (int rr = 0; rr < 2; rr++) {
            int row = gr0 + mt * 16 + rr * 8 + (lane >> 2);
            float rowpart = 0.f;
#pragma unroll
            for (int nt = 0; nt < 4; nt++) {
                int col = gc0 + nt * 8 + (lane & 3) * 2;
                float e0 = __expf(c[mt][nt][rr * 2 + 0]) * 0.0625f;
                float e1 = __expf(c[mt][nt][rr * 2 + 1]) * 0.0625f;
                __half2 h = __floats2half2_rn(e0, e1);
                *reinterpret_cast<__half2*>(&P[(size_t)row * N_TOK + col]) = h;
                float2 f = __half22float2(h);
                rowpart += f.x + f.y;
            }
            rowpart += __shfl_xor_sync(0xffffffffu, rowpart, 1);
            rowpart += __shfl_xor_sync(0xffffffffu, rowpart, 2);
            if ((lane & 3) == 0)
                rsum[wn][wm * 64 + mt * 16 + rr * 8 + (lane >> 2)] = rowpart;
        }
    __syncthreads();
    if (tid < 128) {
        float s = rsum[0][tid] + rsum[1][tid] + rsum[2][tid] + rsum[3][tid];
        rsp[(size_t)(bm * 128 + tid) * 64 + bn] = s;
    }
}

__global__ void rs_reduce_kernel(const float* __restrict__ rsp, float* __restrict__ rs)
{
    const int row = blockIdx.x * 256 + threadIdx.x;
    const float4* p = reinterpret_cast<const float4*>(rsp + (size_t)row * 64);
    float s = 0.f;
#pragma unroll
    for (int i = 0; i < 16; i++) {
        float4 v = p[i];
        s += (v.x + v.y) + (v.z + v.w);
    }
    rs[row] = s;
}

// ===========================================================================
// Fused PV (fp16): tmp = (P' v)/rs' (fp16) ; out_var = (P'^2 vv)/rs'^2 (fp32).
// R12-identical geometry: CTA 128x64, warp 64x16, 2-stage.
// Stage: A 16K | B1 8K | B2 8K = 32K; 2 stages = 64K; 2 CTA/SM.
// ===========================================================================
__global__ void __launch_bounds__(256, 2)
fused_pv_kernel(const __half* __restrict__ P, const __half* __restrict__ vT,
                const __half* __restrict__ vvT, const float* __restrict__ rs,
                __half* __restrict__ tmp, float* __restrict__ out_var)
{
    extern __shared__ char smem_raw[];
    const uint32_t s_base = smem_u32(smem_raw);
    const int tid = threadIdx.x;
    const int warp = tid >> 5, lane = tid & 31;
    const int wm = warp >> 2, wn = warp & 3;
    const int bn = blockIdx.x, bm = blockIdx.y;

    const __half* Ab  = P   + (size_t)bm * 128 * N_TOK;
    const __half* B1b = vT  + (size_t)bn * 64 * N_TOK;
    const __half* B2b = vvT + (size_t)bn * 64 * N_TOK;

    float cm[4][2][4], cv[4][2][4];
#pragma unroll
    for (int i = 0; i < 4; i++)
#pragma unroll
        for (int j = 0; j < 2; j++)
#pragma unroll
            for (int l = 0; l < 4; l++) { cm[i][j][l] = 0.f; cv[i][j][l] = 0.f; }

    auto issue = [&](int stage, int kc) {
        const uint32_t sA  = s_base + (uint32_t)stage * 32768u;
        const uint32_t sB1 = sA + 16384u;
        const uint32_t sB2 = sA + 24576u;
        const int k0 = kc * 64;
#pragma unroll
        for (int i = 0; i < 4; i++) {        // A: 128 rows x 128B = 16K
            int v = tid + i * 256; int row = v >> 3, ch = v & 7;
            uint32_t off = (uint32_t)(row * 128 + ((ch ^ (row & 7)) << 4));
            cp16(sA + off, Ab + (size_t)row * N_TOK + k0 + ch * 8);
        }
#pragma unroll
        for (int i = 0; i < 2; i++) {        // B1/B2: 64 rows x 128B = 8K each
            int v = tid + i * 256; int row = v >> 3, ch = v & 7;
            uint32_t off = (uint32_t)(row * 128 + ((ch ^ (row & 7)) << 4));
            cp16(sB1 + off, B1b + (size_t)row * N_TOK + k0 + ch * 8);
            cp16(sB2 + off, B2b + (size_t)row * N_TOK + k0 + ch * 8);
        }
        asm volatile("cp.async.commit_group;");
    };

    auto compute = [&](int stage) {
        const uint32_t sA  = s_base + (uint32_t)stage * 32768u;
        const uint32_t sB1 = sA + 16384u;
        const uint32_t sB2 = sA + 24576u;
        const int lg = lane >> 3, li = lane & 7;
#pragma unroll
        for (int s = 0; s < 4; s++) {
            const int ch = s * 2 + (lg >> 1);
            uint32_t a[4][4], a2[4][4];
#pragma unroll
            for (int mt = 0; mt < 4; mt++) {
                int row = wm * 64 + mt * 16 + (lg & 1) * 8 + li;
                ldsm4(a[mt], sA + row * 128 + ((ch ^ (row & 7)) << 4));
#pragma unroll
                for (int q = 0; q < 4; q++) a2[mt][q] = hmul2(a[mt][q], a[mt][q]);
            }
            uint32_t b1[4], b2[4];
            {
                int row = wn * 16 + (lg & 1) * 8 + li;
                uint32_t off = (uint32_t)(row * 128 + ((ch ^ (row & 7)) << 4));
                ldsm4(b1, sB1 + off);
                ldsm4(b2, sB2 + off);
            }
#pragma unroll
            for (int mt = 0; mt < 4; mt++)
#pragma unroll
                for (int nt = 0; nt < 2; nt++) {
                    mma_f16(cm[mt][nt], a[mt],  b1[nt], b1[nt + 2]);
                    mma_f16(cv[mt][nt], a2[mt], b2[nt], b2[nt + 2]);
                }
        }
    };

    const int nk = N_TOK / 64;   // 128
    issue(0, 0);
    for (int kc = 0; kc < nk; kc++) {
        if (kc + 1 < nk) { issue((kc + 1) & 1, kc + 1); asm volatile("cp.async.wait_group 1;"); }
        else             { asm volatile("cp.async.wait_group 0;"); }
        __syncthreads();
        compute(kc & 1);
        __syncthreads();
    }

    const int gr0 = bm * 128 + wm * 64;
    const int gc0 = bn * 64 + wn * 16;
#pragma unroll
    for (int mt = 0; mt < 4; mt++)
#pragma unroll
        for (int rr = 0; rr < 2; rr++) {
            int row = gr0 + mt * 16 + rr * 8 + (lane >> 2);
            float rfac = 1.f / rs[row];
            float rfac2 = rfac * rfac;
#pragma unroll
            for (int nt = 0; nt < 2; nt++) {
                int col = gc0 + nt * 8 + (lane & 3) * 2;
                float m0 = cm[mt][nt][rr * 2 + 0] * rfac;
                float m1 = cm[mt][nt][rr * 2 + 1] * rfac;
                *reinterpret_cast<__half2*>(&tmp[(size_t)row * DIM + col]) =
                    __floats2half2_rn(m0, m1);
                float v0 = cv[mt][nt][rr * 2 + 0] * rfac2;
                float v1 = cv[mt][nt][rr * 2 + 1] * rfac2;
                *reinterpret_cast<float2*>(&out_var[(size_t)row * DIM + col]) =
                    make_float2(v0, v1);
            }
        }
}

// ===========================================================================
extern "C" void kernel_launch(void* const* d_in, const int* in_sizes, int n_in,
                              void* d_out, int out_size)
{
    (void)in_sizes; (void)n_in; (void)out_size;
    const float* x_mean = (const float*)d_in[0];
    const float* x_var  = (const float*)d_in[1];
    const float* Wq = (const float*)d_in[4];  const float* bq = (const float*)d_in[5];
    const float* Wk = (const float*)d_in[6];  const float* bk = (const float*)d_in[7];
    const float* Wv = (const float*)d_in[8];  const float* bv = (const float*)d_in[9];
    const float* Wo = (const float*)d_in[10]; const float* bo = (const float*)d_in[11];
    const float* Wvar = (const float*)d_in[12]; const float* bvar = (const float*)d_in[13];

    float* out_mean = (float*)d_out;
    float* out_var  = out_mean + (size_t)N_TOK * DIM;

    __half *xh, *xvh, *wq, *wk, *wv, *wvar, *wo;
    __half *q, *k, *vT, *vvT, *P, *tmp;
    float *rs, *rsp;
    cudaGetSymbolAddress((void**)&xh,   g_xh);
    cudaGetSymbolAddress((void**)&xvh,  g_xvh);
    cudaGetSymbolAddress((void**)&wq,   g_Wqh);
    cudaGetSymbolAddress((void**)&wk,   g_Wkh);
    cudaGetSymbolAddress((void**)&wv,   g_Wvh);
    cudaGetSymbolAddress((void**)&wvar, g_Wvarh);
    cudaGetSymbolAddress((void**)&wo,   g_Woh);
    cudaGetSymbolAddress((void**)&q,    g_q);
    cudaGetSymbolAddress((void**)&k,    g_k);
    cudaGetSymbolAddress((void**)&vT,   g_vT);
    cudaGetSymbolAddress((void**)&vvT,  g_vvT);
    cudaGetSymbolAddress((void**)&tmp,  g_tmp);
    cudaGetSymbolAddress((void**)&P,    g_P);
    cudaGetSymbolAddress((void**)&rs,   g_rs);
    cudaGetSymbolAddress((void**)&rsp,  g_rsp);

    const int SM_PROJ = 49152;   // (16K+8K)*2
    const int SM_QK   = 65536;   // (16K+16K)*2
    const int SM_PV   = 65536;   // (16K+8K+8K)*2

    cudaFuncSetAttribute((const void*)proj_h_kernel<false, true >, cudaFuncAttributeMaxDynamicSharedMemorySize, SM_PROJ);
    cudaFuncSetAttribute((const void*)proj_h_kernel<true,  true >, cudaFuncAttributeMaxDynamicSharedMemorySize, SM_PROJ);
    cudaFuncSetAttribute((const void*)proj_h_kernel<false, false>, cudaFuncAttributeMaxDynamicSharedMemorySize, SM_PROJ);
    cudaFuncSetAttribute((const void*)qk_exp_kernel,   cudaFuncAttributeMaxDynamicSharedMemorySize, SM_QK);
    cudaFuncSetAttribute((const void*)fused_pv_kernel, cudaFuncAttributeMaxDynamicSharedMemorySize, SM_PV);

    // convert inputs + weights to fp16
    cvt_fp16_kernel<<<dim3(128, 7), 256>>>(
        x_mean, x_var, Wq, Wk, Wv, Wvar, Wo,
        xh, xvh, wq, wk, wv, wvar, wo);

    dim3 gProj2(DIM / 64, N_TOK / 128, 2);  // (4, 64, 2)
    dim3 gProj1(DIM / 64, N_TOK / 128, 1);
    dim3 gQK(N_TOK / 128, N_TOK / 128);     // (64, 64)
    dim3 gPV(DIM / 64, N_TOK / 128);        // (4, 64)

    // projections: q (x0.125) + k; vT + vvT (transposed)
    proj_h_kernel<false, true><<<gProj2, 256, SM_PROJ>>>(
        xh, wq, bq, q, 0.125f,  xh, wk, bk, k, 1.f, N_TOK);
    proj_h_kernel<true, true><<<gProj2, 256, SM_PROJ>>>(
        xh, wv, bv, vT, 1.f,    xvh, wvar, bvar, vvT, 1.f, N_TOK);

    qk_exp_kernel<<<gQK, 256, SM_QK>>>(q, k, P, rsp);
    rs_reduce_kernel<<<N_TOK / 256, 256>>>(rsp, rs);

    fused_pv_kernel<<<gPV, 256, SM_PV>>>(P, vT, vvT, rs, tmp, out_var);

    proj_h_kernel<false, false><<<gProj1, 256, SM_PROJ>>>(
        tmp, wo, bo, out_mean, 1.f, tmp, wo, bo, out_mean, 1.f, N_TOK);
}